// round 8
// baseline (speedup 1.0000x reference)
#include <cuda_runtime.h>
#include <cuda_bf16.h>

#define N_NODES 50000
#define N_EDGES 800000
#define D       64
#define ROWS    128        // rows per block in the dense kernel
#define CAP     64         // bucket capacity per node (max degree ~35 for this input)
#define OVF_MAX 4096

// Scratch (__device__ globals; zero-initialized at module load).
// Invariants restored every call: g_cnt zeroed by gather, g_ovf_cnt by dense.
__device__ int  g_cnt[N_NODES];
__device__ int2 g_edge[N_NODES * CAP];   // bucket slots: {src, float_as_int(w)}
__device__ int  g_ovf_cnt;
__device__ int4 g_ovf[OVF_MAX];          // {dst, src, w_bits, pad} overflow spill
__device__ float g_neigh[N_NODES * D];

// packed fp32x2 FMA: d = a*b + d   (Blackwell double-rate fp32 path)
__device__ __forceinline__ void ffma2(unsigned long long& d,
                                      unsigned long long a,
                                      unsigned long long b) {
    asm("fma.rn.f32x2 %0, %1, %2, %0;" : "+l"(d) : "l"(a), "l"(b));
}
__device__ __forceinline__ unsigned long long pack2(float x) {
    unsigned long long r;
    unsigned int xi = __float_as_uint(x);
    asm("mov.b64 %0, {%1, %1};" : "=l"(r) : "r"(xi));
    return r;
}
__device__ __forceinline__ void unpack2(unsigned long long v, float& lo, float& hi) {
    unsigned int a, b;
    asm("mov.b64 {%0, %1}, %2;" : "=r"(a), "=r"(b) : "l"(v));
    lo = __uint_as_float(a);
    hi = __uint_as_float(b);
}

// ---------------------------------------------------------------------------
// K1: bucket-scatter edges, 4 edges/thread.
// Phase 1: 4 independent atomicAdds issued back-to-back (MLP=4 on ATOMG).
// Phase 2: 4 slot stores. Grid is 2x the 8-edge version -> occ ~60%.
// ---------------------------------------------------------------------------
__device__ __forceinline__ void bucket_store(int d, int p, int s, float w) {
    if (p < CAP) {
        g_edge[d * CAP + p] = make_int2(s, __float_as_int(w));
    } else {
        int o = atomicAdd(&g_ovf_cnt, 1);
        if (o < OVF_MAX) g_ovf[o] = make_int4(d, s, __float_as_int(w), 0);
    }
}

__global__ void bucket_kernel(const int4*   __restrict__ src4,
                              const int4*   __restrict__ dst4,
                              const float4* __restrict__ w4) {
    int t = blockIdx.x * blockDim.x + threadIdx.x;
    if (t >= N_EDGES / 4) return;
    int4   s = src4[t];
    int4   d = dst4[t];
    float4 w = w4[t];

    // front-batched independent atomics
    int p0 = atomicAdd(&g_cnt[d.x], 1);
    int p1 = atomicAdd(&g_cnt[d.y], 1);
    int p2 = atomicAdd(&g_cnt[d.z], 1);
    int p3 = atomicAdd(&g_cnt[d.w], 1);

    bucket_store(d.x, p0, s.x, w.x);
    bucket_store(d.y, p1, s.y, w.y);
    bucket_store(d.z, p2, s.z, w.z);
    bucket_store(d.w, p3, s.w, w.w);
}

// ---------------------------------------------------------------------------
// K2: gather-side segment reduce over buckets. One warp per node; lane l
// owns dims 2l, 2l+1. Meta staged in per-warp smem; inner loop preloads
// up to 16 rows (typical node = ONE L2 latency round). Resets g_cnt.
// ---------------------------------------------------------------------------
#define GW 8   // warps per gather block
__global__ __launch_bounds__(GW * 32)
void gather_kernel(const float* __restrict__ h) {
    __shared__ int2 sE[GW][32];
    int wslot = threadIdx.x >> 5;
    int warp  = (blockIdx.x * blockDim.x + threadIdx.x) >> 5;
    int lane  = threadIdx.x & 31;
    if (warp >= N_NODES) return;

    int cnt = g_cnt[warp];
    int m   = min(cnt, CAP);
    const int2* bucket = g_edge + warp * CAP;

    float2 acc = make_float2(0.f, 0.f);
    const float* hl = h + 2 * lane;

    for (int e0 = 0; e0 < m; e0 += 32) {
        int n = min(32, m - e0);
        if (lane < n) sE[wslot][lane] = bucket[e0 + lane];
        __syncwarp();
        for (int j = 0; j < n; j += 16) {
            int nb = min(16, n - j);
            float2 hv[16];
            float  ww[16];
#pragma unroll
            for (int q = 0; q < 16; q++) {
                if (q < nb) {
                    int2 e = sE[wslot][j + q];
                    ww[q] = __int_as_float(e.y);
                    hv[q] = *reinterpret_cast<const float2*>(hl + (size_t)e.x * D);
                }
            }
#pragma unroll
            for (int q = 0; q < 16; q++) {
                if (q < nb) {
                    acc.x = fmaf(ww[q], hv[q].x, acc.x);
                    acc.y = fmaf(ww[q], hv[q].y, acc.y);
                }
            }
        }
        __syncwarp();
    }

    // Overflow safety net (never taken for this input; correctness guard)
    if (cnt > CAP) {
        int oc = min(g_ovf_cnt, OVF_MAX);
        for (int i = 0; i < oc; i++) {
            int4 e = g_ovf[i];
            if (e.x == warp) {
                float ww = __int_as_float(e.z);
                float2 hv = *reinterpret_cast<const float2*>(hl + (size_t)e.y * D);
                acc.x = fmaf(ww, hv.x, acc.x);
                acc.y = fmaf(ww, hv.y, acc.y);
            }
        }
    }

    *reinterpret_cast<float2*>(g_neigh + (size_t)warp * D + 2 * lane) = acc;
    if (lane == 0) g_cnt[warp] = 0;          // restore invariant
}

// ---------------------------------------------------------------------------
// K3: dense  out = relu([h | neigh] @ [W_self | W_neigh]^T + b) — unchanged
// (ffma2-packed accumulators, broadcast LDS.128 weights, padded sX staging).
// Also resets g_ovf_cnt (runs after gather in stream order).
// ---------------------------------------------------------------------------
__global__ __launch_bounds__(ROWS)
void dense_kernel(const float* __restrict__ h,
                  const float* __restrict__ Ws, const float* __restrict__ bs,
                  const float* __restrict__ Wn, const float* __restrict__ bn,
                  float* __restrict__ out) {
    __shared__ __align__(16) float sW[128 * 64];  // sW[k*64+j]
    __shared__ float sX[32][ROWS + 1];
    __shared__ float sB[64];

    const int tid     = threadIdx.x;
    const int rowBase = blockIdx.x * ROWS;
    const int row     = rowBase + tid;
    const bool valid  = row < N_NODES;

    if (blockIdx.x == 0 && tid == 0) g_ovf_cnt = 0;   // restore invariant

    for (int idx = tid; idx < 128 * 64; idx += ROWS) {
        int k = idx >> 6, j = idx & 63;
        sW[idx] = (k < 64) ? Ws[j * 64 + k] : Wn[j * 64 + (k - 64)];
    }
    if (tid < 64) sB[tid] = bs[tid] + bn[tid];

    unsigned long long acc[32];
#pragma unroll
    for (int p = 0; p < 32; p++) acc[p] = 0ull;

    const int lane = tid & 31;
    const int rq   = tid >> 5;

    for (int kc = 0; kc < 4; kc++) {
        const float* srcp = (kc < 2) ? h : g_neigh;
        const int colBase = (kc & 1) * 32;

        __syncthreads();

        for (int r = rq; r < ROWS; r += ROWS / 32) {
            int rr = rowBase + r;
            float val = (rr < N_NODES) ? srcp[(size_t)rr * D + colBase + lane] : 0.f;
            sX[lane][r] = val;
        }
        __syncthreads();

#pragma unroll 2
        for (int kk = 0; kk < 32; kk++) {
            unsigned long long xx = pack2(sX[kk][tid]);
            const ulonglong2* wrow = reinterpret_cast<const ulonglong2*>(
                sW + (kc * 32 + kk) * 64);
#pragma unroll
            for (int q = 0; q < 16; q++) {
                ulonglong2 wv = wrow[q];      // broadcast LDS.128 -> 2 packed pairs
                ffma2(acc[2 * q + 0], xx, wv.x);
                ffma2(acc[2 * q + 1], xx, wv.y);
            }
        }
    }

    if (valid) {
        float4* op = reinterpret_cast<float4*>(out + (size_t)row * D);
#pragma unroll
        for (int q4 = 0; q4 < 16; q4++) {
            float a, b, c, d;
            unpack2(acc[2 * q4 + 0], a, b);
            unpack2(acc[2 * q4 + 1], c, d);
            float4 o;
            o.x = fmaxf(a + sB[4 * q4 + 0], 0.f);
            o.y = fmaxf(b + sB[4 * q4 + 1], 0.f);
            o.z = fmaxf(c + sB[4 * q4 + 2], 0.f);
            o.w = fmaxf(d + sB[4 * q4 + 3], 0.f);
            op[q4] = o;
        }
    }
}

// ---------------------------------------------------------------------------
// kernel_launch
//   0: h [N,D] f32   1: edge_src [E] i32   2: edge_dst [E] i32   3: edge_w [E] f32
//   4: W_self [D,D]  5: b_self [D]         6: W_neigh [D,D]      7: b_neigh [D]
// ---------------------------------------------------------------------------
extern "C" void kernel_launch(void* const* d_in, const int* in_sizes, int n_in,
                              void* d_out, int out_size) {
    const float* h        = (const float*)d_in[0];
    const int*   edge_src = (const int*)  d_in[1];
    const int*   edge_dst = (const int*)  d_in[2];
    const float* edge_w   = (const float*)d_in[3];
    const float* W_self   = (const float*)d_in[4];
    const float* b_self   = (const float*)d_in[5];
    const float* W_neigh  = (const float*)d_in[6];
    const float* b_neigh  = (const float*)d_in[7];
    float* out = (float*)d_out;

    {
        // 4 edges per thread
        int threadsTotal = N_EDGES / 4;
        int blocks = (threadsTotal + 255) / 256;
        bucket_kernel<<<blocks, 256>>>((const int4*)edge_src, (const int4*)edge_dst,
                                       (const float4*)edge_w);
    }

    {
        int blocks = (N_NODES + GW - 1) / GW;
        gather_kernel<<<blocks, GW * 32>>>(h);
    }

    {
        int blocks = (N_NODES + ROWS - 1) / ROWS;
        dense_kernel<<<blocks, ROWS>>>(h, W_self, b_self, W_neigh, b_neigh, out);
    }
}

// round 9
// speedup vs baseline: 1.0148x; 1.0148x over previous
#include <cuda_runtime.h>
#include <cuda_bf16.h>

#define N_NODES 50000
#define N_EDGES 800000
#define D       64
#define ROWS    128        // rows per block in the dense kernel
#define CAP     64         // bucket capacity per node (max degree ~35 for this input)
#define OVF_MAX 4096

// Scratch (__device__ globals; zero-initialized at module load).
// Invariants restored every call: g_cnt zeroed by gather, g_ovf_cnt by reset.
__device__ int  g_cnt[N_NODES];
__device__ int2 g_edge[N_NODES * CAP];   // bucket slots: {src, float_as_int(w)}
__device__ int  g_ovf_cnt;
__device__ int4 g_ovf[OVF_MAX];          // {dst, src, w_bits, pad} overflow spill
__device__ float g_neigh[N_NODES * D];

// packed fp32x2 FMA: d = a*b + d   (Blackwell double-rate fp32 path)
__device__ __forceinline__ void ffma2(unsigned long long& d,
                                      unsigned long long a,
                                      unsigned long long b) {
    asm("fma.rn.f32x2 %0, %1, %2, %0;" : "+l"(d) : "l"(a), "l"(b));
}
__device__ __forceinline__ unsigned long long pack2(float x) {
    unsigned long long r;
    unsigned int xi = __float_as_uint(x);
    asm("mov.b64 %0, {%1, %1};" : "=l"(r) : "r"(xi));
    return r;
}
__device__ __forceinline__ void unpack2(unsigned long long v, float& lo, float& hi) {
    unsigned int a, b;
    asm("mov.b64 {%0, %1}, %2;" : "=r"(a), "=r"(b) : "l"(v));
    lo = __uint_as_float(a);
    hi = __uint_as_float(b);
}

// ---------------------------------------------------------------------------
// K0: tiny reset (also shifts dense to the 4th launch so ncu profiles it)
// ---------------------------------------------------------------------------
__global__ void reset_kernel() {
    if (threadIdx.x == 0 && blockIdx.x == 0) g_ovf_cnt = 0;
}

// ---------------------------------------------------------------------------
// K1: bucket-scatter edges (R7 configuration: 8 edges/thread, interleaved).
// ---------------------------------------------------------------------------
__device__ __forceinline__ void bucket_put(int d, int s, float w) {
    int p = atomicAdd(&g_cnt[d], 1);
    if (p < CAP) {
        g_edge[d * CAP + p] = make_int2(s, __float_as_int(w));
    } else {
        int o = atomicAdd(&g_ovf_cnt, 1);
        if (o < OVF_MAX) g_ovf[o] = make_int4(d, s, __float_as_int(w), 0);
    }
}

__global__ void bucket_kernel(const int4*   __restrict__ src4,
                              const int4*   __restrict__ dst4,
                              const float4* __restrict__ w4) {
    int t = blockIdx.x * blockDim.x + threadIdx.x;
    int base = t * 2;                       // 2 int4 groups = 8 edges
    const int NQ = N_EDGES / 4;
#pragma unroll
    for (int g = 0; g < 2; g++) {
        int q = base + g;
        if (q < NQ) {
            int4   s = src4[q];
            int4   d = dst4[q];
            float4 w = w4[q];
            bucket_put(d.x, s.x, w.x);
            bucket_put(d.y, s.y, w.y);
            bucket_put(d.z, s.z, w.z);
            bucket_put(d.w, s.w, w.w);
        }
    }
}

// ---------------------------------------------------------------------------
// K2: gather-side segment reduce over buckets (R7 configuration, MLP=8).
// One warp per node; lane l owns dims 2l, 2l+1. Resets g_cnt.
// ---------------------------------------------------------------------------
#define GW 8   // warps per gather block
__global__ __launch_bounds__(GW * 32)
void gather_kernel(const float* __restrict__ h) {
    __shared__ int2 sE[GW][32];
    int wslot = threadIdx.x >> 5;
    int warp  = (blockIdx.x * blockDim.x + threadIdx.x) >> 5;
    int lane  = threadIdx.x & 31;
    if (warp >= N_NODES) return;

    int cnt = g_cnt[warp];
    int m   = min(cnt, CAP);
    const int2* bucket = g_edge + warp * CAP;

    float2 acc = make_float2(0.f, 0.f);
    const float* hl = h + 2 * lane;

    for (int e0 = 0; e0 < m; e0 += 32) {
        int n = min(32, m - e0);
        if (lane < n) sE[wslot][lane] = bucket[e0 + lane];
        __syncwarp();
        int j = 0;
        for (; j + 8 <= n; j += 8) {
            float2 hv[8];
            float  ww[8];
#pragma unroll
            for (int q = 0; q < 8; q++) {
                int2 e = sE[wslot][j + q];
                ww[q] = __int_as_float(e.y);
                hv[q] = *reinterpret_cast<const float2*>(hl + (size_t)e.x * D);
            }
#pragma unroll
            for (int q = 0; q < 8; q++) {
                acc.x = fmaf(ww[q], hv[q].x, acc.x);
                acc.y = fmaf(ww[q], hv[q].y, acc.y);
            }
        }
        if (j < n) {
            float2 hv[7];
            float  ww[7];
            int mm = n - j;
#pragma unroll
            for (int q = 0; q < 7; q++) {
                if (q < mm) {
                    int2 e = sE[wslot][j + q];
                    ww[q] = __int_as_float(e.y);
                    hv[q] = *reinterpret_cast<const float2*>(hl + (size_t)e.x * D);
                }
            }
#pragma unroll
            for (int q = 0; q < 7; q++) {
                if (q < mm) {
                    acc.x = fmaf(ww[q], hv[q].x, acc.x);
                    acc.y = fmaf(ww[q], hv[q].y, acc.y);
                }
            }
        }
        __syncwarp();
    }

    // Overflow safety net (never taken for this input; correctness guard)
    if (cnt > CAP) {
        int oc = min(g_ovf_cnt, OVF_MAX);
        for (int i = 0; i < oc; i++) {
            int4 e = g_ovf[i];
            if (e.x == warp) {
                float ww = __int_as_float(e.z);
                float2 hv = *reinterpret_cast<const float2*>(hl + (size_t)e.y * D);
                acc.x = fmaf(ww, hv.x, acc.x);
                acc.y = fmaf(ww, hv.y, acc.y);
            }
        }
    }

    *reinterpret_cast<float2*>(g_neigh + (size_t)warp * D + 2 * lane) = acc;
    if (lane == 0) g_cnt[warp] = 0;          // restore invariant
}

// ---------------------------------------------------------------------------
// K3: dense  out = relu([h | neigh] @ [W_self | W_neigh]^T + b)
// (ffma2-packed accumulators, broadcast LDS.128 weights, padded sX staging)
// Now the 4th launch -> gets profiled; regs/dur diagnose the ffma2 path.
// ---------------------------------------------------------------------------
__global__ __launch_bounds__(ROWS)
void dense_kernel(const float* __restrict__ h,
                  const float* __restrict__ Ws, const float* __restrict__ bs,
                  const float* __restrict__ Wn, const float* __restrict__ bn,
                  float* __restrict__ out) {
    __shared__ __align__(16) float sW[128 * 64];  // sW[k*64+j]
    __shared__ float sX[32][ROWS + 1];
    __shared__ float sB[64];

    const int tid     = threadIdx.x;
    const int rowBase = blockIdx.x * ROWS;
    const int row     = rowBase + tid;
    const bool valid  = row < N_NODES;

    for (int idx = tid; idx < 128 * 64; idx += ROWS) {
        int k = idx >> 6, j = idx & 63;
        sW[idx] = (k < 64) ? Ws[j * 64 + k] : Wn[j * 64 + (k - 64)];
    }
    if (tid < 64) sB[tid] = bs[tid] + bn[tid];

    unsigned long long acc[32];
#pragma unroll
    for (int p = 0; p < 32; p++) acc[p] = 0ull;

    const int lane = tid & 31;
    const int rq   = tid >> 5;

    for (int kc = 0; kc < 4; kc++) {
        const float* srcp = (kc < 2) ? h : g_neigh;
        const int colBase = (kc & 1) * 32;

        __syncthreads();

        for (int r = rq; r < ROWS; r += ROWS / 32) {
            int rr = rowBase + r;
            float val = (rr < N_NODES) ? srcp[(size_t)rr * D + colBase + lane] : 0.f;
            sX[lane][r] = val;
        }
        __syncthreads();

#pragma unroll 2
        for (int kk = 0; kk < 32; kk++) {
            unsigned long long xx = pack2(sX[kk][tid]);
            const ulonglong2* wrow = reinterpret_cast<const ulonglong2*>(
                sW + (kc * 32 + kk) * 64);
#pragma unroll
            for (int q = 0; q < 16; q++) {
                ulonglong2 wv = wrow[q];      // broadcast LDS.128 -> 2 packed pairs
                ffma2(acc[2 * q + 0], xx, wv.x);
                ffma2(acc[2 * q + 1], xx, wv.y);
            }
        }
    }

    if (valid) {
        float4* op = reinterpret_cast<float4*>(out + (size_t)row * D);
#pragma unroll
        for (int q4 = 0; q4 < 16; q4++) {
            float a, b, c, d;
            unpack2(acc[2 * q4 + 0], a, b);
            unpack2(acc[2 * q4 + 1], c, d);
            float4 o;
            o.x = fmaxf(a + sB[4 * q4 + 0], 0.f);
            o.y = fmaxf(b + sB[4 * q4 + 1], 0.f);
            o.z = fmaxf(c + sB[4 * q4 + 2], 0.f);
            o.w = fmaxf(d + sB[4 * q4 + 3], 0.f);
            op[q4] = o;
        }
    }
}

// ---------------------------------------------------------------------------
// kernel_launch
//   0: h [N,D] f32   1: edge_src [E] i32   2: edge_dst [E] i32   3: edge_w [E] f32
//   4: W_self [D,D]  5: b_self [D]         6: W_neigh [D,D]      7: b_neigh [D]
// ---------------------------------------------------------------------------
extern "C" void kernel_launch(void* const* d_in, const int* in_sizes, int n_in,
                              void* d_out, int out_size) {
    const float* h        = (const float*)d_in[0];
    const int*   edge_src = (const int*)  d_in[1];
    const int*   edge_dst = (const int*)  d_in[2];
    const float* edge_w   = (const float*)d_in[3];
    const float* W_self   = (const float*)d_in[4];
    const float* b_self   = (const float*)d_in[5];
    const float* W_neigh  = (const float*)d_in[6];
    const float* b_neigh  = (const float*)d_in[7];
    float* out = (float*)d_out;

    reset_kernel<<<1, 32>>>();

    {
        // 8 edges per thread (R7 configuration)
        int threadsTotal = N_EDGES / 8;
        int blocks = (threadsTotal + 255) / 256;
        bucket_kernel<<<blocks, 256>>>((const int4*)edge_src, (const int4*)edge_dst,
                                       (const float4*)edge_w);
    }

    {
        int blocks = (N_NODES + GW - 1) / GW;
        gather_kernel<<<blocks, GW * 32>>>(h);
    }

    {
        int blocks = (N_NODES + ROWS - 1) / ROWS;
        dense_kernel<<<blocks, ROWS>>>(h, W_self, b_self, W_neigh, b_neigh, out);
    }
}

// round 10
// speedup vs baseline: 1.0208x; 1.0059x over previous
#include <cuda_runtime.h>
#include <cuda_bf16.h>

#define N_NODES 50000
#define N_EDGES 800000
#define D       64
#define ROWS    128        // rows per dense block
#define DBLOCK  256        // dense threads: 2 threads per row
#define CAP     64         // bucket capacity per node (max degree ~35 for this input)
#define OVF_MAX 4096

// Scratch (__device__ globals; zero-initialized at module load).
// Invariants restored every call: g_cnt zeroed by gather, g_ovf_cnt by reset.
__device__ int  g_cnt[N_NODES];
__device__ int2 g_edge[N_NODES * CAP];   // bucket slots: {src, float_as_int(w)}
__device__ int  g_ovf_cnt;
__device__ int4 g_ovf[OVF_MAX];          // {dst, src, w_bits, pad} overflow spill
__device__ float g_neigh[N_NODES * D];

// ---------------------------------------------------------------------------
// K0: tiny reset (keeps dense as the 4th launch so ncu profiles it)
// ---------------------------------------------------------------------------
__global__ void reset_kernel() {
    if (threadIdx.x == 0 && blockIdx.x == 0) g_ovf_cnt = 0;
}

// ---------------------------------------------------------------------------
// K1: bucket-scatter edges (R7 configuration: 8 edges/thread, interleaved).
// ---------------------------------------------------------------------------
__device__ __forceinline__ void bucket_put(int d, int s, float w) {
    int p = atomicAdd(&g_cnt[d], 1);
    if (p < CAP) {
        g_edge[d * CAP + p] = make_int2(s, __float_as_int(w));
    } else {
        int o = atomicAdd(&g_ovf_cnt, 1);
        if (o < OVF_MAX) g_ovf[o] = make_int4(d, s, __float_as_int(w), 0);
    }
}

__global__ void bucket_kernel(const int4*   __restrict__ src4,
                              const int4*   __restrict__ dst4,
                              const float4* __restrict__ w4) {
    int t = blockIdx.x * blockDim.x + threadIdx.x;
    int base = t * 2;                       // 2 int4 groups = 8 edges
    const int NQ = N_EDGES / 4;
#pragma unroll
    for (int g = 0; g < 2; g++) {
        int q = base + g;
        if (q < NQ) {
            int4   s = src4[q];
            int4   d = dst4[q];
            float4 w = w4[q];
            bucket_put(d.x, s.x, w.x);
            bucket_put(d.y, s.y, w.y);
            bucket_put(d.z, s.z, w.z);
            bucket_put(d.w, s.w, w.w);
        }
    }
}

// ---------------------------------------------------------------------------
// K2: gather-side segment reduce over buckets (R7 configuration, MLP=8).
// One warp per node; lane l owns dims 2l, 2l+1. Resets g_cnt.
// ---------------------------------------------------------------------------
#define GW 8   // warps per gather block
__global__ __launch_bounds__(GW * 32)
void gather_kernel(const float* __restrict__ h) {
    __shared__ int2 sE[GW][32];
    int wslot = threadIdx.x >> 5;
    int warp  = (blockIdx.x * blockDim.x + threadIdx.x) >> 5;
    int lane  = threadIdx.x & 31;
    if (warp >= N_NODES) return;

    int cnt = g_cnt[warp];
    int m   = min(cnt, CAP);
    const int2* bucket = g_edge + warp * CAP;

    float2 acc = make_float2(0.f, 0.f);
    const float* hl = h + 2 * lane;

    for (int e0 = 0; e0 < m; e0 += 32) {
        int n = min(32, m - e0);
        if (lane < n) sE[wslot][lane] = bucket[e0 + lane];
        __syncwarp();
        int j = 0;
        for (; j + 8 <= n; j += 8) {
            float2 hv[8];
            float  ww[8];
#pragma unroll
            for (int q = 0; q < 8; q++) {
                int2 e = sE[wslot][j + q];
                ww[q] = __int_as_float(e.y);
                hv[q] = *reinterpret_cast<const float2*>(hl + (size_t)e.x * D);
            }
#pragma unroll
            for (int q = 0; q < 8; q++) {
                acc.x = fmaf(ww[q], hv[q].x, acc.x);
                acc.y = fmaf(ww[q], hv[q].y, acc.y);
            }
        }
        if (j < n) {
            float2 hv[7];
            float  ww[7];
            int mm = n - j;
#pragma unroll
            for (int q = 0; q < 7; q++) {
                if (q < mm) {
                    int2 e = sE[wslot][j + q];
                    ww[q] = __int_as_float(e.y);
                    hv[q] = *reinterpret_cast<const float2*>(hl + (size_t)e.x * D);
                }
            }
#pragma unroll
            for (int q = 0; q < 7; q++) {
                if (q < mm) {
                    acc.x = fmaf(ww[q], hv[q].x, acc.x);
                    acc.y = fmaf(ww[q], hv[q].y, acc.y);
                }
            }
        }
        __syncwarp();
    }

    // Overflow safety net (never taken for this input; correctness guard)
    if (cnt > CAP) {
        int oc = min(g_ovf_cnt, OVF_MAX);
        for (int i = 0; i < oc; i++) {
            int4 e = g_ovf[i];
            if (e.x == warp) {
                float ww = __int_as_float(e.z);
                float2 hv = *reinterpret_cast<const float2*>(hl + (size_t)e.y * D);
                acc.x = fmaf(ww, hv.x, acc.x);
                acc.y = fmaf(ww, hv.y, acc.y);
            }
        }
    }

    *reinterpret_cast<float2*>(g_neigh + (size_t)warp * D + 2 * lane) = acc;
    if (lane == 0) g_cnt[warp] = 0;          // restore invariant
}

// ---------------------------------------------------------------------------
// K3: dense  out = relu([h | neigh] @ [W_self | W_neigh]^T + b)
// 2 threads per output row: thread owns 32 outputs (j-half), full K=128.
// Plain FFMA (ffma2 falsified twice: asm b64 pairs -> 128 regs + MOV churn).
// acc=32 regs -> ~2x warps/SM vs R9. Weight LDS.128 stays warp-broadcast
// (j-half uniform per warp); sX reads stride-1 conflict-free.
// ---------------------------------------------------------------------------
__global__ __launch_bounds__(DBLOCK)
void dense_kernel(const float* __restrict__ h,
                  const float* __restrict__ Ws, const float* __restrict__ bs,
                  const float* __restrict__ Wn, const float* __restrict__ bn,
                  float* __restrict__ out) {
    __shared__ __align__(16) float sW[128 * 64];  // sW[k*64+j]
    __shared__ float sX[32][ROWS + 1];
    __shared__ float sB[64];

    const int tid     = threadIdx.x;
    const int rlocal  = tid & (ROWS - 1);   // row within block
    const int half    = tid >> 7;           // j-half: 0 -> [0,32), 1 -> [32,64)
    const int rowBase = blockIdx.x * ROWS;
    const int row     = rowBase + rlocal;
    const bool valid  = row < N_NODES;

    for (int idx = tid; idx < 128 * 64; idx += DBLOCK) {
        int k = idx >> 6, j = idx & 63;
        sW[idx] = (k < 64) ? Ws[j * 64 + k] : Wn[j * 64 + (k - 64)];
    }
    if (tid < 64) sB[tid] = bs[tid] + bn[tid];

    float acc[32];
#pragma unroll
    for (int j = 0; j < 32; j++) acc[j] = 0.f;

    const int lane = tid & 31;   // k offset within chunk (coalesced load dim)
    const int rq   = tid >> 5;   // row phase (0..7)

    for (int kc = 0; kc < 4; kc++) {
        const float* srcp = (kc < 2) ? h : g_neigh;
        const int colBase = (kc & 1) * 32;

        __syncthreads();  // protect sX reuse (covers sW/sB on first iter)

        // Stage: sX[k][r] = x[rowBase + r][kc*32 + k], coalesced global reads
        for (int r = rq; r < ROWS; r += DBLOCK / 32) {
            int rr = rowBase + r;
            float val = (rr < N_NODES) ? srcp[(size_t)rr * D + colBase + lane] : 0.f;
            sX[lane][r] = val;
        }
        __syncthreads();

        const float4* sW4 = reinterpret_cast<const float4*>(sW)
                          + kc * 32 * 16 + half * 8;
#pragma unroll 4
        for (int kk = 0; kk < 32; kk++) {
            float x = sX[kk][rlocal];
            const float4* wrow = sW4 + kk * 16;
#pragma unroll
            for (int j4 = 0; j4 < 8; j4++) {
                float4 wv = wrow[j4];     // broadcast LDS.128
                acc[4 * j4 + 0] = fmaf(x, wv.x, acc[4 * j4 + 0]);
                acc[4 * j4 + 1] = fmaf(x, wv.y, acc[4 * j4 + 1]);
                acc[4 * j4 + 2] = fmaf(x, wv.z, acc[4 * j4 + 2]);
                acc[4 * j4 + 3] = fmaf(x, wv.w, acc[4 * j4 + 3]);
            }
        }
    }

    if (valid) {
        float4* op = reinterpret_cast<float4*>(out + (size_t)row * D + half * 32);
        const float* bb = sB + half * 32;
#pragma unroll
        for (int j4 = 0; j4 < 8; j4++) {
            float4 o;
            o.x = fmaxf(acc[4 * j4 + 0] + bb[4 * j4 + 0], 0.f);
            o.y = fmaxf(acc[4 * j4 + 1] + bb[4 * j4 + 1], 0.f);
            o.z = fmaxf(acc[4 * j4 + 2] + bb[4 * j4 + 2], 0.f);
            o.w = fmaxf(acc[4 * j4 + 3] + bb[4 * j4 + 3], 0.f);
            op[j4] = o;
        }
    }
}

// ---------------------------------------------------------------------------
// kernel_launch
//   0: h [N,D] f32   1: edge_src [E] i32   2: edge_dst [E] i32   3: edge_w [E] f32
//   4: W_self [D,D]  5: b_self [D]         6: W_neigh [D,D]      7: b_neigh [D]
// ---------------------------------------------------------------------------
extern "C" void kernel_launch(void* const* d_in, const int* in_sizes, int n_in,
                              void* d_out, int out_size) {
    const float* h        = (const float*)d_in[0];
    const int*   edge_src = (const int*)  d_in[1];
    const int*   edge_dst = (const int*)  d_in[2];
    const float* edge_w   = (const float*)d_in[3];
    const float* W_self   = (const float*)d_in[4];
    const float* b_self   = (const float*)d_in[5];
    const float* W_neigh  = (const float*)d_in[6];
    const float* b_neigh  = (const float*)d_in[7];
    float* out = (float*)d_out;

    reset_kernel<<<1, 32>>>();

    {
        // 8 edges per thread (R7 configuration)
        int threadsTotal = N_EDGES / 8;
        int blocks = (threadsTotal + 255) / 256;
        bucket_kernel<<<blocks, 256>>>((const int4*)edge_src, (const int4*)edge_dst,
                                       (const float4*)edge_w);
    }

    {
        int blocks = (N_NODES + GW - 1) / GW;
        gather_kernel<<<blocks, GW * 32>>>(h);
    }

    {
        int blocks = (N_NODES + ROWS - 1) / ROWS;
        dense_kernel<<<blocks, DBLOCK>>>(h, W_self, b_self, W_neigh, b_neigh, out);
    }
}

// round 11
// speedup vs baseline: 1.0403x; 1.0191x over previous
#include <cuda_runtime.h>
#include <cuda_bf16.h>

#define N_NODES 50000
#define N_EDGES 800000
#define D       64
#define ROWS    128        // rows per dense block
#define DBLOCK  256        // dense threads (each owns 4 rows x 8 cols)
#define SXPAD   132        // sX row stride in floats (528B -> 16B aligned)
#define CAP     64         // bucket capacity per node (max degree ~35 for this input)
#define OVF_MAX 4096

// Scratch (__device__ globals; zero-initialized at module load).
// Invariants restored every call: g_cnt zeroed by gather, g_ovf_cnt by reset.
__device__ int  g_cnt[N_NODES];
__device__ int2 g_edge[N_NODES * CAP];   // bucket slots: {src, float_as_int(w)}
__device__ int  g_ovf_cnt;
__device__ int4 g_ovf[OVF_MAX];          // {dst, src, w_bits, pad} overflow spill
__device__ float g_neigh[N_NODES * D];

// ---------------------------------------------------------------------------
// K0: tiny reset (keeps dense as the 4th launch so ncu profiles it)
// ---------------------------------------------------------------------------
__global__ void reset_kernel() {
    if (threadIdx.x == 0 && blockIdx.x == 0) g_ovf_cnt = 0;
}

// ---------------------------------------------------------------------------
// K1: bucket-scatter edges (R7 configuration: 8 edges/thread, interleaved).
// ---------------------------------------------------------------------------
__device__ __forceinline__ void bucket_put(int d, int s, float w) {
    int p = atomicAdd(&g_cnt[d], 1);
    if (p < CAP) {
        g_edge[d * CAP + p] = make_int2(s, __float_as_int(w));
    } else {
        int o = atomicAdd(&g_ovf_cnt, 1);
        if (o < OVF_MAX) g_ovf[o] = make_int4(d, s, __float_as_int(w), 0);
    }
}

__global__ void bucket_kernel(const int4*   __restrict__ src4,
                              const int4*   __restrict__ dst4,
                              const float4* __restrict__ w4) {
    int t = blockIdx.x * blockDim.x + threadIdx.x;
    int base = t * 2;                       // 2 int4 groups = 8 edges
    const int NQ = N_EDGES / 4;
#pragma unroll
    for (int g = 0; g < 2; g++) {
        int q = base + g;
        if (q < NQ) {
            int4   s = src4[q];
            int4   d = dst4[q];
            float4 w = w4[q];
            bucket_put(d.x, s.x, w.x);
            bucket_put(d.y, s.y, w.y);
            bucket_put(d.z, s.z, w.z);
            bucket_put(d.w, s.w, w.w);
        }
    }
}

// ---------------------------------------------------------------------------
// K2: gather-side segment reduce over buckets (R7 configuration, MLP=8).
// One warp per node; lane l owns dims 2l, 2l+1. Resets g_cnt.
// ---------------------------------------------------------------------------
#define GW 8   // warps per gather block
__global__ __launch_bounds__(GW * 32)
void gather_kernel(const float* __restrict__ h) {
    __shared__ int2 sE[GW][32];
    int wslot = threadIdx.x >> 5;
    int warp  = (blockIdx.x * blockDim.x + threadIdx.x) >> 5;
    int lane  = threadIdx.x & 31;
    if (warp >= N_NODES) return;

    int cnt = g_cnt[warp];
    int m   = min(cnt, CAP);
    const int2* bucket = g_edge + warp * CAP;

    float2 acc = make_float2(0.f, 0.f);
    const float* hl = h + 2 * lane;

    for (int e0 = 0; e0 < m; e0 += 32) {
        int n = min(32, m - e0);
        if (lane < n) sE[wslot][lane] = bucket[e0 + lane];
        __syncwarp();
        int j = 0;
        for (; j + 8 <= n; j += 8) {
            float2 hv[8];
            float  ww[8];
#pragma unroll
            for (int q = 0; q < 8; q++) {
                int2 e = sE[wslot][j + q];
                ww[q] = __int_as_float(e.y);
                hv[q] = *reinterpret_cast<const float2*>(hl + (size_t)e.x * D);
            }
#pragma unroll
            for (int q = 0; q < 8; q++) {
                acc.x = fmaf(ww[q], hv[q].x, acc.x);
                acc.y = fmaf(ww[q], hv[q].y, acc.y);
            }
        }
        if (j < n) {
            float2 hv[7];
            float  ww[7];
            int mm = n - j;
#pragma unroll
            for (int q = 0; q < 7; q++) {
                if (q < mm) {
                    int2 e = sE[wslot][j + q];
                    ww[q] = __int_as_float(e.y);
                    hv[q] = *reinterpret_cast<const float2*>(hl + (size_t)e.x * D);
                }
            }
#pragma unroll
            for (int q = 0; q < 7; q++) {
                if (q < mm) {
                    acc.x = fmaf(ww[q], hv[q].x, acc.x);
                    acc.y = fmaf(ww[q], hv[q].y, acc.y);
                }
            }
        }
        __syncwarp();
    }

    // Overflow safety net (never taken for this input; correctness guard)
    if (cnt > CAP) {
        int oc = min(g_ovf_cnt, OVF_MAX);
        for (int i = 0; i < oc; i++) {
            int4 e = g_ovf[i];
            if (e.x == warp) {
                float ww = __int_as_float(e.z);
                float2 hv = *reinterpret_cast<const float2*>(hl + (size_t)e.y * D);
                acc.x = fmaf(ww, hv.x, acc.x);
                acc.y = fmaf(ww, hv.y, acc.y);
            }
        }
    }

    *reinterpret_cast<float2*>(g_neigh + (size_t)warp * D + 2 * lane) = acc;
    if (lane == 0) g_cnt[warp] = 0;          // restore invariant
}

// ---------------------------------------------------------------------------
// K3: dense  out = relu([h | neigh] @ [W_self | W_neigh]^T + b)
// Register-tiled: each thread owns a 4-row x 8-col output tile.
//   cg = tid & 7  -> cols [8cg, 8cg+8)
//   rg = tid >> 3 -> rows [4rg, 4rg+4)
// Per k: 1 LDS.128 (x, 4 rows) + 2 LDS.128 (w, 8 cols) -> 32 FFMA.
// sX layout [k][row] pad 132 -> 16B-aligned rows, conflict-free reads.
// ---------------------------------------------------------------------------
__global__ __launch_bounds__(DBLOCK)
void dense_kernel(const float* __restrict__ h,
                  const float* __restrict__ Ws, const float* __restrict__ bs,
                  const float* __restrict__ Wn, const float* __restrict__ bn,
                  float* __restrict__ out) {
    __shared__ __align__(16) float sW[128 * 64];     // sW[k*64+j]
    __shared__ __align__(16) float sX[32 * SXPAD];   // sX[k*132 + row]
    __shared__ float sB[64];

    const int tid     = threadIdx.x;
    const int cg      = tid & 7;             // col group (8 cols)
    const int rg      = tid >> 3;            // row group (4 rows)
    const int rowBase = blockIdx.x * ROWS;

    for (int idx = tid; idx < 128 * 64; idx += DBLOCK) {
        int k = idx >> 6, j = idx & 63;
        sW[idx] = (k < 64) ? Ws[j * 64 + k] : Wn[j * 64 + (k - 64)];
    }
    if (tid < 64) sB[tid] = bs[tid] + bn[tid];

    float acc[4][8];
#pragma unroll
    for (int i = 0; i < 4; i++)
#pragma unroll
        for (int j = 0; j < 8; j++) acc[i][j] = 0.f;

    for (int kc = 0; kc < 4; kc++) {
        const float* srcp = (kc < 2) ? h : g_neigh;
        const int colBase = (kc & 1) * 32;

        __syncthreads();  // protect sX reuse (covers sW/sB on first iter)

        // Stage 32k x 128rows: 1024 float4 along k, coalesced global reads,
        // scattered STS into [k][row] (<=4-way bank conflict, amortized).
#pragma unroll
        for (int p = 0; p < 4; p++) {
            int f  = tid + DBLOCK * p;       // float4 index 0..1023
            int r  = f >> 3;                 // row 0..127
            int k4 = (f & 7) * 4;            // k offset 0,4,..,28
            int rr = rowBase + r;
            float4 v = make_float4(0.f, 0.f, 0.f, 0.f);
            if (rr < N_NODES)
                v = *reinterpret_cast<const float4*>(srcp + (size_t)rr * D + colBase + k4);
            sX[(k4 + 0) * SXPAD + r] = v.x;
            sX[(k4 + 1) * SXPAD + r] = v.y;
            sX[(k4 + 2) * SXPAD + r] = v.z;
            sX[(k4 + 3) * SXPAD + r] = v.w;
        }
        __syncthreads();

        const float4* wbase = reinterpret_cast<const float4*>(sW + kc * 32 * 64) + cg * 2;
        const float*  xbase = sX + rg * 4;

#pragma unroll 4
        for (int kk = 0; kk < 32; kk++) {
            float4 xv = *reinterpret_cast<const float4*>(xbase + kk * SXPAD);
            float4 wa = wbase[kk * 16 + 0];
            float4 wb = wbase[kk * 16 + 1];
            float w8[8] = {wa.x, wa.y, wa.z, wa.w, wb.x, wb.y, wb.z, wb.w};
            float x4[4] = {xv.x, xv.y, xv.z, xv.w};
#pragma unroll
            for (int i = 0; i < 4; i++)
#pragma unroll
                for (int j = 0; j < 8; j++)
                    acc[i][j] = fmaf(x4[i], w8[j], acc[i][j]);
        }
    }

    // Epilogue: bias + relu, 2x STG.128 per row
    float bj[8];
#pragma unroll
    for (int j = 0; j < 8; j++) bj[j] = sB[cg * 8 + j];

#pragma unroll
    for (int i = 0; i < 4; i++) {
        int rr = rowBase + rg * 4 + i;
        if (rr < N_NODES) {
            float4 o0, o1;
            o0.x = fmaxf(acc[i][0] + bj[0], 0.f);
            o0.y = fmaxf(acc[i][1] + bj[1], 0.f);
            o0.z = fmaxf(acc[i][2] + bj[2], 0.f);
            o0.w = fmaxf(acc[i][3] + bj[3], 0.f);
            o1.x = fmaxf(acc[i][4] + bj[4], 0.f);
            o1.y = fmaxf(acc[i][5] + bj[5], 0.f);
            o1.z = fmaxf(acc[i][6] + bj[6], 0.f);
            o1.w = fmaxf(acc[i][7] + bj[7], 0.f);
            float4* op = reinterpret_cast<float4*>(out + (size_t)rr * D + cg * 8);
            op[0] = o0;
            op[1] = o1;
        }
    }
}

// ---------------------------------------------------------------------------
// kernel_launch
//   0: h [N,D] f32   1: edge_src [E] i32   2: edge_dst [E] i32   3: edge_w [E] f32
//   4: W_self [D,D]  5: b_self [D]         6: W_neigh [D,D]      7: b_neigh [D]
// ---------------------------------------------------------------------------
extern "C" void kernel_launch(void* const* d_in, const int* in_sizes, int n_in,
                              void* d_out, int out_size) {
    const float* h        = (const float*)d_in[0];
    const int*   edge_src = (const int*)  d_in[1];
    const int*   edge_dst = (const int*)  d_in[2];
    const float* edge_w   = (const float*)d_in[3];
    const float* W_self   = (const float*)d_in[4];
    const float* b_self   = (const float*)d_in[5];
    const float* W_neigh  = (const float*)d_in[6];
    const float* b_neigh  = (const float*)d_in[7];
    float* out = (float*)d_out;

    reset_kernel<<<1, 32>>>();

    {
        // 8 edges per thread (R7 configuration)
        int threadsTotal = N_EDGES / 8;
        int blocks = (threadsTotal + 255) / 256;
        bucket_kernel<<<blocks, 256>>>((const int4*)edge_src, (const int4*)edge_dst,
                                       (const float4*)edge_w);
    }

    {
        int blocks = (N_NODES + GW - 1) / GW;
        gather_kernel<<<blocks, GW * 32>>>(h);
    }

    {
        int blocks = (N_NODES + ROWS - 1) / ROWS;
        dense_kernel<<<blocks, DBLOCK>>>(h, W_self, b_self, W_neigh, b_neigh, out);
    }
}

// round 12
// speedup vs baseline: 1.1576x; 1.1128x over previous
#include <cuda_runtime.h>
#include <cuda_bf16.h>

#define N_NODES 50000
#define N_EDGES 800000
#define D       64
#define ROWS    64         // rows per dense block
#define DBLOCK  256        // dense threads (each owns 2 rows x 8 cols)
#define WSTRIDE 68         // floats per k-row of sW (17 float4: 16 slots + pad)
#define XSTRIDE 68         // floats per k-row of sX
#define CAP     64         // bucket capacity per node (max degree ~35 for this input)
#define OVF_MAX 4096

// Scratch (__device__ globals; zero-initialized at module load).
// Invariants restored every call: g_cnt zeroed by gather, g_ovf_cnt by reset.
__device__ int  g_cnt[N_NODES];
__device__ int2 g_edge[N_NODES * CAP];   // bucket slots: {src, float_as_int(w)}
__device__ int  g_ovf_cnt;
__device__ int4 g_ovf[OVF_MAX];          // {dst, src, w_bits, pad} overflow spill
__device__ float g_neigh[N_NODES * D];

// ---------------------------------------------------------------------------
// K0: tiny reset (keeps dense as the 4th launch so ncu profiles it)
// ---------------------------------------------------------------------------
__global__ void reset_kernel() {
    if (threadIdx.x == 0 && blockIdx.x == 0) g_ovf_cnt = 0;
}

// ---------------------------------------------------------------------------
// K1: bucket-scatter edges (R7 configuration: 8 edges/thread, interleaved).
// ---------------------------------------------------------------------------
__device__ __forceinline__ void bucket_put(int d, int s, float w) {
    int p = atomicAdd(&g_cnt[d], 1);
    if (p < CAP) {
        g_edge[d * CAP + p] = make_int2(s, __float_as_int(w));
    } else {
        int o = atomicAdd(&g_ovf_cnt, 1);
        if (o < OVF_MAX) g_ovf[o] = make_int4(d, s, __float_as_int(w), 0);
    }
}

__global__ void bucket_kernel(const int4*   __restrict__ src4,
                              const int4*   __restrict__ dst4,
                              const float4* __restrict__ w4) {
    int t = blockIdx.x * blockDim.x + threadIdx.x;
    int base = t * 2;                       // 2 int4 groups = 8 edges
    const int NQ = N_EDGES / 4;
#pragma unroll
    for (int g = 0; g < 2; g++) {
        int q = base + g;
        if (q < NQ) {
            int4   s = src4[q];
            int4   d = dst4[q];
            float4 w = w4[q];
            bucket_put(d.x, s.x, w.x);
            bucket_put(d.y, s.y, w.y);
            bucket_put(d.z, s.z, w.z);
            bucket_put(d.w, s.w, w.w);
        }
    }
}

// ---------------------------------------------------------------------------
// K2: gather-side segment reduce over buckets (R7 configuration, MLP=8).
// One warp per node; lane l owns dims 2l, 2l+1. Resets g_cnt.
// ---------------------------------------------------------------------------
#define GW 8   // warps per gather block
__global__ __launch_bounds__(GW * 32)
void gather_kernel(const float* __restrict__ h) {
    __shared__ int2 sE[GW][32];
    int wslot = threadIdx.x >> 5;
    int warp  = (blockIdx.x * blockDim.x + threadIdx.x) >> 5;
    int lane  = threadIdx.x & 31;
    if (warp >= N_NODES) return;

    int cnt = g_cnt[warp];
    int m   = min(cnt, CAP);
    const int2* bucket = g_edge + warp * CAP;

    float2 acc = make_float2(0.f, 0.f);
    const float* hl = h + 2 * lane;

    for (int e0 = 0; e0 < m; e0 += 32) {
        int n = min(32, m - e0);
        if (lane < n) sE[wslot][lane] = bucket[e0 + lane];
        __syncwarp();
        int j = 0;
        for (; j + 8 <= n; j += 8) {
            float2 hv[8];
            float  ww[8];
#pragma unroll
            for (int q = 0; q < 8; q++) {
                int2 e = sE[wslot][j + q];
                ww[q] = __int_as_float(e.y);
                hv[q] = *reinterpret_cast<const float2*>(hl + (size_t)e.x * D);
            }
#pragma unroll
            for (int q = 0; q < 8; q++) {
                acc.x = fmaf(ww[q], hv[q].x, acc.x);
                acc.y = fmaf(ww[q], hv[q].y, acc.y);
            }
        }
        if (j < n) {
            float2 hv[7];
            float  ww[7];
            int mm = n - j;
#pragma unroll
            for (int q = 0; q < 7; q++) {
                if (q < mm) {
                    int2 e = sE[wslot][j + q];
                    ww[q] = __int_as_float(e.y);
                    hv[q] = *reinterpret_cast<const float2*>(hl + (size_t)e.x * D);
                }
            }
#pragma unroll
            for (int q = 0; q < 7; q++) {
                if (q < mm) {
                    acc.x = fmaf(ww[q], hv[q].x, acc.x);
                    acc.y = fmaf(ww[q], hv[q].y, acc.y);
                }
            }
        }
        __syncwarp();
    }

    // Overflow safety net (never taken for this input; correctness guard)
    if (cnt > CAP) {
        int oc = min(g_ovf_cnt, OVF_MAX);
        for (int i = 0; i < oc; i++) {
            int4 e = g_ovf[i];
            if (e.x == warp) {
                float ww = __int_as_float(e.z);
                float2 hv = *reinterpret_cast<const float2*>(hl + (size_t)e.y * D);
                acc.x = fmaf(ww, hv.x, acc.x);
                acc.y = fmaf(ww, hv.y, acc.y);
            }
        }
    }

    *reinterpret_cast<float2*>(g_neigh + (size_t)warp * D + 2 * lane) = acc;
    if (lane == 0) g_cnt[warp] = 0;          // restore invariant
}

// ---------------------------------------------------------------------------
// K3: dense  out = relu([h | neigh] @ [W_self | W_neigh]^T + b)
// Tile 2 rows x 8 cols per thread; ROWS=64 per block -> grid 782 (~5 blk/SM,
// ~40 warps/SM). Per kk: LDS.64 (x, broadcast) + 2x LDS.128 (w, slot-
// interleaved -> conflict-free) -> 16 FFMA.
//   sW[k][slot]: col j -> slot (j>>3) + ((j>>2)&1)*8, elem j&3; stride 68.
//   sX[k][r^swz(k)]: swz(k) = ((k>>3)&3)<<2 -> STS staging hits 32 banks.
// ---------------------------------------------------------------------------
__global__ __launch_bounds__(DBLOCK)
void dense_kernel(const float* __restrict__ h,
                  const float* __restrict__ Ws, const float* __restrict__ bs,
                  const float* __restrict__ Wn, const float* __restrict__ bn,
                  float* __restrict__ out) {
    __shared__ __align__(16) float sW[128 * WSTRIDE];
    __shared__ __align__(16) float sX[32 * XSTRIDE];
    __shared__ float sB[64];

    const int tid     = threadIdx.x;
    const int cg      = tid & 7;      // col group: cols [8cg, 8cg+8)
    const int rg      = tid >> 3;     // row group: rows {2rg, 2rg+1}
    const int rowBase = blockIdx.x * ROWS;

    // Fill sW: consecutive tid -> consecutive k (coalesced 128B global reads).
    // idx: kk = k within matrix (0..63), j = col, m = 0:Ws / 1:Wn.
    for (int idx = tid; idx < 128 * 64; idx += DBLOCK) {
        int kk = idx & 63;
        int j  = (idx >> 6) & 63;
        int m  = idx >> 12;
        float v = m ? Wn[j * 64 + kk] : Ws[j * 64 + kk];
        int slot = (j >> 3) + ((j >> 2) & 1) * 8;
        sW[(m * 64 + kk) * WSTRIDE + slot * 4 + (j & 3)] = v;
    }
    if (tid < 64) sB[tid] = bs[tid] + bn[tid];

    float acc[2][8];
#pragma unroll
    for (int i = 0; i < 2; i++)
#pragma unroll
        for (int j = 0; j < 8; j++) acc[i][j] = 0.f;

    for (int kc = 0; kc < 4; kc++) {
        const float* srcp = (kc < 2) ? h : g_neigh;
        const int colBase = (kc & 1) * 32;

        __syncthreads();  // protect sX reuse (covers sW/sB on first iter)

        // Stage 64 rows x 32 k: 512 float4, 2 per thread; coalesced loads,
        // XOR-swizzled scatter (conflict-free STS, proven 32 distinct banks).
#pragma unroll
        for (int p = 0; p < 2; p++) {
            int f  = tid + DBLOCK * p;       // float4 index 0..511
            int r  = f >> 3;                 // row 0..63
            int k4 = (f & 7) * 4;            // k offset 0,4,..,28
            int rr = rowBase + r;
            float4 v = make_float4(0.f, 0.f, 0.f, 0.f);
            if (rr < N_NODES)
                v = *reinterpret_cast<const float4*>(srcp + (size_t)rr * D + colBase + k4);
#pragma unroll
            for (int i = 0; i < 4; i++) {
                int k  = k4 + i;
                int sz = ((k >> 3) & 3) << 2;
                float vi = (i == 0) ? v.x : (i == 1) ? v.y : (i == 2) ? v.z : v.w;
                sX[k * XSTRIDE + (r ^ sz)] = vi;
            }
        }
        __syncthreads();

        const float4* wbase = reinterpret_cast<const float4*>(sW) + (kc * 32) * 17 + cg;

#pragma unroll 4
        for (int kk = 0; kk < 32; kk++) {
            int sz = ((kk >> 3) & 3) << 2;
            float2 xv = *reinterpret_cast<const float2*>(sX + kk * XSTRIDE + ((rg * 2) ^ sz));
            float4 wa = wbase[kk * 17];          // slots cg   -> cols 8cg..8cg+3
            float4 wb = wbase[kk * 17 + 8];      // slot  cg+8 -> cols 8cg+4..8cg+7
            float w8[8] = {wa.x, wa.y, wa.z, wa.w, wb.x, wb.y, wb.z, wb.w};
#pragma unroll
            for (int j = 0; j < 8; j++) {
                acc[0][j] = fmaf(xv.x, w8[j], acc[0][j]);
                acc[1][j] = fmaf(xv.y, w8[j], acc[1][j]);
            }
        }
    }

    // Epilogue: bias + relu, 2x STG.128 per row
    float bj[8];
#pragma unroll
    for (int j = 0; j < 8; j++) bj[j] = sB[cg * 8 + j];

#pragma unroll
    for (int i = 0; i < 2; i++) {
        int rr = rowBase + rg * 2 + i;
        if (rr < N_NODES) {
            float4 o0, o1;
            o0.x = fmaxf(acc[i][0] + bj[0], 0.f);
            o0.y = fmaxf(acc[i][1] + bj[1], 0.f);
            o0.z = fmaxf(acc[i][2] + bj[2], 0.f);
            o0.w = fmaxf(acc[i][3] + bj[3], 0.f);
            o1.x = fmaxf(acc[i][4] + bj[4], 0.f);
            o1.y = fmaxf(acc[i][5] + bj[5], 0.f);
            o1.z = fmaxf(acc[i][6] + bj[6], 0.f);
            o1.w = fmaxf(acc[i][7] + bj[7], 0.f);
            float4* op = reinterpret_cast<float4*>(out + (size_t)rr * D + cg * 8);
            op[0] = o0;
            op[1] = o1;
        }
    }
}

// ---------------------------------------------------------------------------
// kernel_launch
//   0: h [N,D] f32   1: edge_src [E] i32   2: edge_dst [E] i32   3: edge_w [E] f32
//   4: W_self [D,D]  5: b_self [D]         6: W_neigh [D,D]      7: b_neigh [D]
// ---------------------------------------------------------------------------
extern "C" void kernel_launch(void* const* d_in, const int* in_sizes, int n_in,
                              void* d_out, int out_size) {
    const float* h        = (const float*)d_in[0];
    const int*   edge_src = (const int*)  d_in[1];
    const int*   edge_dst = (const int*)  d_in[2];
    const float* edge_w   = (const float*)d_in[3];
    const float* W_self   = (const float*)d_in[4];
    const float* b_self   = (const float*)d_in[5];
    const float* W_neigh  = (const float*)d_in[6];
    const float* b_neigh  = (const float*)d_in[7];
    float* out = (float*)d_out;

    reset_kernel<<<1, 32>>>();

    {
        // 8 edges per thread (R7 configuration)
        int threadsTotal = N_EDGES / 8;
        int blocks = (threadsTotal + 255) / 256;
        bucket_kernel<<<blocks, 256>>>((const int4*)edge_src, (const int4*)edge_dst,
                                       (const float4*)edge_w);
    }

    {
        int blocks = (N_NODES + GW - 1) / GW;
        gather_kernel<<<blocks, GW * 32>>>(h);
    }

    {
        int blocks = (N_NODES + ROWS - 1) / ROWS;
        dense_kernel<<<blocks, DBLOCK>>>(h, W_self, b_self, W_neigh, b_neigh, out);
    }
}